// round 8
// baseline (speedup 1.0000x reference)
#include <cuda_runtime.h>
#include <cstdint>

#define NB 32
#define NT 512
#define ND 512
#define NH 1024
#define NM (NB*NT)   // 16384 rows

typedef unsigned long long ull;

// ---- scratch (device globals; no runtime allocation allowed) ----
__device__ float         g_h1[(size_t)NM * NH];   // 64 MB fc1 raw output
__device__ unsigned char g_s1[(size_t)NM * NH];   // 16 MB spikes layer 1
__device__ float         g_y [(size_t)NM * ND];   // 32 MB fc2+ln2 out
__device__ float         g_w2t[(size_t)NH * ND];  //  2 MB w2 transposed to [H, D]
__device__ float         g_mean[NM];              // ln1 row means
__device__ float         g_inv [NM];              // ln1 row inv-std

// ---- packed fp32x2 helpers (Blackwell FFMA2, identical per-lane fp32 rounding) ----
__device__ __forceinline__ ull pack2(float lo, float hi) {
    ull r;
    asm("mov.b64 %0, {%1, %2};" : "=l"(r)
        : "r"(__float_as_uint(lo)), "r"(__float_as_uint(hi)));
    return r;
}
__device__ __forceinline__ void unpack2(ull v, float& lo, float& hi) {
    unsigned a, b;
    asm("mov.b64 {%0, %1}, %2;" : "=r"(a), "=r"(b) : "l"(v));
    lo = __uint_as_float(a); hi = __uint_as_float(b);
}
__device__ __forceinline__ ull fma2(ull a, ull b, ull c) {
    ull d;
    asm("fma.rn.f32x2 %0, %1, %2, %3;" : "=l"(d) : "l"(a), "l"(b), "l"(c));
    return d;
}

// ============================================================================
// GEMM1: g_h1[m,n] = sum_k x[m,k]*w1[n,k] + b1[n]
// Block tile 128m x 256n, BK=16, 256 threads, 8m x 16n per thread.
// f32x2 packed accumulators (pairs along n), ascending-k (bitwise-exact).
// ============================================================================
__global__ __launch_bounds__(256) void gemm1_kernel(const float* __restrict__ A,
                                                    const float* __restrict__ W,
                                                    const float* __restrict__ bias) {
    __shared__ __align__(16) float As[16][132];
    __shared__ __align__(16) float Bs[16][260];
    const int tid  = threadIdx.x;
    const int row0 = blockIdx.y * 128;
    const int col0 = blockIdx.x * 256;
    const int tx = tid & 15;        // n-dir: 16 cols x 16 threads
    const int ty = tid >> 4;        // m-dir: 8 rows x 16 threads
    const int lma = tid >> 1;       // A loader row 0..127
    const int lka = (tid & 1) * 8;  // A loader col base 0 / 8
    const int lnb = tid;            // B loader row 0..255

    const float* Ap = A + (size_t)(row0 + lma) * ND + lka;
    const float* Bp = W + (size_t)(col0 + lnb) * ND;

    ull acc[8][8];
#pragma unroll
    for (int i = 0; i < 8; i++)
#pragma unroll
        for (int j = 0; j < 8; j++) acc[i][j] = 0ull;

    float4 pa0 = ((const float4*)Ap)[0];
    float4 pa1 = ((const float4*)Ap)[1];
    float4 pb0 = ((const float4*)Bp)[0];
    float4 pb1 = ((const float4*)Bp)[1];
    float4 pb2 = ((const float4*)Bp)[2];
    float4 pb3 = ((const float4*)Bp)[3];

#pragma unroll 1
    for (int kt = 0; kt < 32; kt++) {
        As[lka + 0][lma] = pa0.x; As[lka + 1][lma] = pa0.y;
        As[lka + 2][lma] = pa0.z; As[lka + 3][lma] = pa0.w;
        As[lka + 4][lma] = pa1.x; As[lka + 5][lma] = pa1.y;
        As[lka + 6][lma] = pa1.z; As[lka + 7][lma] = pa1.w;
        Bs[ 0][lnb] = pb0.x; Bs[ 1][lnb] = pb0.y; Bs[ 2][lnb] = pb0.z; Bs[ 3][lnb] = pb0.w;
        Bs[ 4][lnb] = pb1.x; Bs[ 5][lnb] = pb1.y; Bs[ 6][lnb] = pb1.z; Bs[ 7][lnb] = pb1.w;
        Bs[ 8][lnb] = pb2.x; Bs[ 9][lnb] = pb2.y; Bs[10][lnb] = pb2.z; Bs[11][lnb] = pb2.w;
        Bs[12][lnb] = pb3.x; Bs[13][lnb] = pb3.y; Bs[14][lnb] = pb3.z; Bs[15][lnb] = pb3.w;
        __syncthreads();

        if (kt < 31) {
            const float* Ap2 = Ap + (kt + 1) * 16;
            const float* Bp2 = Bp + (kt + 1) * 16;
            pa0 = ((const float4*)Ap2)[0];
            pa1 = ((const float4*)Ap2)[1];
            pb0 = ((const float4*)Bp2)[0];
            pb1 = ((const float4*)Bp2)[1];
            pb2 = ((const float4*)Bp2)[2];
            pb3 = ((const float4*)Bp2)[3];
        }

#pragma unroll
        for (int kk = 0; kk < 16; kk++) {
            float4 a0 = *(const float4*)&As[kk][ty * 8];
            float4 a1 = *(const float4*)&As[kk][ty * 8 + 4];
            ulonglong2 b01 = *(const ulonglong2*)&Bs[kk][tx * 16];
            ulonglong2 b23 = *(const ulonglong2*)&Bs[kk][tx * 16 + 4];
            ulonglong2 b45 = *(const ulonglong2*)&Bs[kk][tx * 16 + 8];
            ulonglong2 b67 = *(const ulonglong2*)&Bs[kk][tx * 16 + 12];
            float av[8] = {a0.x, a0.y, a0.z, a0.w, a1.x, a1.y, a1.z, a1.w};
#pragma unroll
            for (int i = 0; i < 8; i++) {
                ull aa = pack2(av[i], av[i]);
                acc[i][0] = fma2(aa, b01.x, acc[i][0]);
                acc[i][1] = fma2(aa, b01.y, acc[i][1]);
                acc[i][2] = fma2(aa, b23.x, acc[i][2]);
                acc[i][3] = fma2(aa, b23.y, acc[i][3]);
                acc[i][4] = fma2(aa, b45.x, acc[i][4]);
                acc[i][5] = fma2(aa, b45.y, acc[i][5]);
                acc[i][6] = fma2(aa, b67.x, acc[i][6]);
                acc[i][7] = fma2(aa, b67.y, acc[i][7]);
            }
        }
        __syncthreads();
    }

    float bv[16];
#pragma unroll
    for (int j = 0; j < 16; j++) bv[j] = bias[col0 + tx * 16 + j];
#pragma unroll
    for (int i = 0; i < 8; i++) {
        float o[16];
#pragma unroll
        for (int j = 0; j < 8; j++) unpack2(acc[i][j], o[2 * j], o[2 * j + 1]);
#pragma unroll
        for (int j = 0; j < 16; j++) o[j] += bv[j];
        float* cp = g_h1 + (size_t)(row0 + ty * 8 + i) * NH + col0 + tx * 16;
        ((float4*)cp)[0] = make_float4(o[0],  o[1],  o[2],  o[3]);
        ((float4*)cp)[1] = make_float4(o[4],  o[5],  o[6],  o[7]);
        ((float4*)cp)[2] = make_float4(o[8],  o[9],  o[10], o[11]);
        ((float4*)cp)[3] = make_float4(o[12], o[13], o[14], o[15]);
    }
}

// ============================================================================
// block-wide reduction (blockDim multiple of 32, <= 256)
// ============================================================================
__device__ __forceinline__ float block_reduce_sum(float val) {
    __shared__ float sm[32];
    const int tid = threadIdx.x;
#pragma unroll
    for (int o = 16; o; o >>= 1) val += __shfl_down_sync(0xffffffffu, val, o);
    if ((tid & 31) == 0) sm[tid >> 5] = val;
    __syncthreads();
    if (tid < 32) {
        const int nw = (blockDim.x + 31) >> 5;
        float v = (tid < nw) ? sm[tid] : 0.f;
#pragma unroll
        for (int o = 4; o; o >>= 1) v += __shfl_down_sync(0xffffffffu, v, o);
        if (tid == 0) sm[0] = v;
    }
    __syncthreads();
    float r = sm[0];
    __syncthreads();
    return r;
}

// ============================================================================
// LN1 stats only: mean & inv-std per row of g_h1.
// ============================================================================
__global__ __launch_bounds__(256) void ln1_stats_kernel() {
    const float* p = g_h1 + (size_t)blockIdx.x * NH;
    const int tid = threadIdx.x;
    float4 v = ((const float4*)p)[tid];
    float s = (v.x + v.y) + (v.z + v.w);
    float total = block_reduce_sum(s);
    float mean = total * (1.0f / NH);
    float d0 = v.x - mean, d1 = v.y - mean, d2 = v.z - mean, d3 = v.w - mean;
    float sq = (d0 * d0 + d1 * d1) + (d2 * d2 + d3 * d3);
    float tot2 = block_reduce_sum(sq);
    float inv = 1.0f / sqrtf(tot2 * (1.0f / NH) + 1e-5f);
    if (tid == 0) { g_mean[blockIdx.x] = mean; g_inv[blockIdx.x] = inv; }
}

// ============================================================================
// LIF layer 1 with inline LayerNorm (R4-verified byte-spike version).
// ============================================================================
__global__ __launch_bounds__(128) void lif1_kernel(const float* __restrict__ g1,
                                                   const float* __restrict__ be1) {
    const int idx = blockIdx.x * 128 + threadIdx.x;   // NB*NH = 32768
    const int b = idx >> 10;
    const int h = idx & (NH - 1);
    const int tid = threadIdx.x;

    __shared__ float s_mean[NT];
    __shared__ float s_inv[NT];
#pragma unroll
    for (int t = tid; t < NT; t += 128) {
        s_mean[t] = g_mean[b * NT + t];
        s_inv[t]  = g_inv [b * NT + t];
    }
    __syncthreads();

    const float gh  = g1[h];
    const float beh = be1[h];
    const float* p = g_h1 + (size_t)b * NT * NH + h;
    unsigned char* q = g_s1 + (size_t)b * NT * NH + h;
    float v = 0.f;
#pragma unroll 1
    for (int t0 = 0; t0 < NT; t0 += 16) {
        float xb[16];
#pragma unroll
        for (int i = 0; i < 16; i++) xb[i] = p[(size_t)(t0 + i) * NH];
        unsigned char sb[16];
#pragma unroll
        for (int i = 0; i < 16; i++) {
            float d = xb[i] - s_mean[t0 + i];
            float val = d * s_inv[t0 + i] * gh + beh;
            v = v + (val - v) * 0.5f;       // TAU = 2
            bool sp = (v >= 1.0f);          // V_TH = 1
            sb[i] = sp ? (unsigned char)1 : (unsigned char)0;
            v = sp ? 0.f : v;               // hard reset
        }
#pragma unroll
        for (int i = 0; i < 16; i++) q[(size_t)(t0 + i) * NH] = sb[i];
    }
}

// ============================================================================
// fc2 (sparse gmem gather, L1-resident w2t) + fused LayerNorm2 (R4-verified).
// ============================================================================
__global__ __launch_bounds__(128) void fc2ln2_kernel(const float* __restrict__ b2,
                                                     const float* __restrict__ g2,
                                                     const float* __restrict__ be2) {
    const int row = blockIdx.x;
    const int tid = threadIdx.x;
    const unsigned char* srow = g_s1 + (size_t)row * NH;

    ull m8 = ((const ull*)srow)[tid];           // 8 spike bytes
    int c = __popcll(m8);
    int pre = c;
#pragma unroll
    for (int o = 1; o < 32; o <<= 1) {
        int n = __shfl_up_sync(0xffffffffu, pre, o);
        if ((tid & 31) >= o) pre += n;
    }
    __shared__ int wsum[4];
    __shared__ unsigned short list[NH];
    __shared__ int s_total;
    if ((tid & 31) == 31) wsum[tid >> 5] = pre;
    __syncthreads();
    int base = 0;
#pragma unroll
    for (int w = 0; w < 4; w++)
        if (w < (tid >> 5)) base += wsum[w];
    int off = base + pre - c;
#pragma unroll
    for (int k = 0; k < 8; k++)
        if ((m8 >> (8 * k)) & 1ull) list[off++] = (unsigned short)(tid * 8 + k);
    if (tid == 127) s_total = base + pre;
    __syncthreads();

    const int cnt = s_total;
    const float* wbase = g_w2t + tid * 4;
    float4 acc = make_float4(0.f, 0.f, 0.f, 0.f);
    int i = 0;
    for (; i + 4 <= cnt; i += 4) {
        int h0 = list[i], h1 = list[i + 1], h2 = list[i + 2], h3 = list[i + 3];
        float4 w0 = *(const float4*)(wbase + (size_t)h0 * ND);
        float4 w1 = *(const float4*)(wbase + (size_t)h1 * ND);
        float4 w2v = *(const float4*)(wbase + (size_t)h2 * ND);
        float4 w3 = *(const float4*)(wbase + (size_t)h3 * ND);
        acc.x += w0.x; acc.y += w0.y; acc.z += w0.z; acc.w += w0.w;
        acc.x += w1.x; acc.y += w1.y; acc.z += w1.z; acc.w += w1.w;
        acc.x += w2v.x; acc.y += w2v.y; acc.z += w2v.z; acc.w += w2v.w;
        acc.x += w3.x; acc.y += w3.y; acc.z += w3.z; acc.w += w3.w;
    }
    for (; i < cnt; i++) {
        float4 w0 = *(const float4*)(wbase + (size_t)list[i] * ND);
        acc.x += w0.x; acc.y += w0.y; acc.z += w0.z; acc.w += w0.w;
    }
    float4 bb = ((const float4*)b2)[tid];
    acc.x += bb.x; acc.y += bb.y; acc.z += bb.z; acc.w += bb.w;

    // ---- fused LayerNorm2 ----
    float s = (acc.x + acc.y) + (acc.z + acc.w);
    float total = block_reduce_sum(s);
    float mean = total * (1.0f / ND);
    float d0 = acc.x - mean, d1 = acc.y - mean, d2 = acc.z - mean, d3 = acc.w - mean;
    float sq = (d0 * d0 + d1 * d1) + (d2 * d2 + d3 * d3);
    float tot2 = block_reduce_sum(sq);
    float inv = 1.0f / sqrtf(tot2 * (1.0f / ND) + 1e-5f);
    float4 gg = ((const float4*)g2)[tid];
    float4 bv = ((const float4*)be2)[tid];
    float4 o;
    o.x = d0 * inv * gg.x + bv.x;
    o.y = d1 * inv * gg.y + bv.y;
    o.z = d2 * inv * gg.z + bv.z;
    o.w = d3 * inv * gg.w + bv.w;
    ((float4*)(g_y + (size_t)row * ND))[tid] = o;
}

// ============================================================================
// LIF layer 2 + residual (R4-verified 16-deep config): out = x + spike2.
// ============================================================================
__global__ __launch_bounds__(64) void lif2_kernel(const float* __restrict__ x,
                                                  float* __restrict__ out) {
    const int idx = blockIdx.x * 64 + threadIdx.x;    // NB*ND = 16384
    const int b = idx >> 9;
    const int d = idx & (ND - 1);
    const float* py = g_y + (size_t)b * NT * ND + d;
    const float* px = x + (size_t)b * NT * ND + d;
    float* po = out + (size_t)b * NT * ND + d;
    float v = 0.f;
#pragma unroll 1
    for (int t0 = 0; t0 < NT; t0 += 16) {
        float yb[16], xb[16];
#pragma unroll
        for (int i = 0; i < 16; i++) yb[i] = py[(size_t)(t0 + i) * ND];
#pragma unroll
        for (int i = 0; i < 16; i++) xb[i] = px[(size_t)(t0 + i) * ND];
        float ob[16];
#pragma unroll
        for (int i = 0; i < 16; i++) {
            v = v + (yb[i] - v) * 0.5f;
            bool sp = (v >= 1.0f);
            ob[i] = xb[i] + (sp ? 1.0f : 0.0f);
            v = sp ? 0.f : v;
        }
#pragma unroll
        for (int i = 0; i < 16; i++) po[(size_t)(t0 + i) * ND] = ob[i];
    }
}

// ============================================================================
// w2 [D, H] -> g_w2t [H, D]
// ============================================================================
__global__ void transpose_kernel(const float* __restrict__ w2) {
    __shared__ float tile[32][33];
    const int h0 = blockIdx.x * 32;
    const int d0 = blockIdx.y * 32;
    tile[threadIdx.y][threadIdx.x] = w2[(size_t)(d0 + threadIdx.y) * NH + h0 + threadIdx.x];
    __syncthreads();
    g_w2t[(size_t)(h0 + threadIdx.y) * ND + d0 + threadIdx.x] = tile[threadIdx.x][threadIdx.y];
}

// ============================================================================
extern "C" void kernel_launch(void* const* d_in, const int* in_sizes, int n_in,
                              void* d_out, int out_size) {
    const float* x   = (const float*)d_in[0];
    const float* w1  = (const float*)d_in[1];
    const float* b1  = (const float*)d_in[2];
    const float* g1  = (const float*)d_in[3];
    const float* be1 = (const float*)d_in[4];
    const float* w2  = (const float*)d_in[5];
    const float* b2  = (const float*)d_in[6];
    const float* g2  = (const float*)d_in[7];
    const float* be2 = (const float*)d_in[8];
    float* out = (float*)d_out;

    transpose_kernel<<<dim3(NH / 32, ND / 32), dim3(32, 32)>>>(w2);
    gemm1_kernel<<<dim3(NH / 256, NM / 128), 256>>>(x, w1, b1);
    ln1_stats_kernel<<<NM, 256>>>();
    lif1_kernel<<<(NB * NH) / 128, 128>>>(g1, be1);
    fc2ln2_kernel<<<NM, 128>>>(b2, g2, be2);
    lif2_kernel<<<(NB * ND) / 64, 64>>>(x, out);
}

// round 9
// speedup vs baseline: 1.6271x; 1.6271x over previous
#include <cuda_runtime.h>
#include <cstdint>

#define NB 32
#define NT 512
#define ND 512
#define NH 1024
#define NM (NB*NT)   // 16384 rows

typedef unsigned long long ull;

// ---- scratch (device globals; no runtime allocation allowed) ----
__device__ float         g_h1[(size_t)NM * NH];   // 64 MB fc1 raw output
__device__ unsigned char g_s1[(size_t)NM * NH];   // 16 MB spikes layer 1
__device__ float         g_y [(size_t)NM * ND];   // 32 MB fc2+ln2 out
__device__ float         g_w2t[(size_t)NH * ND];  //  2 MB w2 transposed to [H, D]
__device__ float         g_mean[NM];              // ln1 row means
__device__ float         g_inv [NM];              // ln1 row inv-std

// ---- packed fp32x2 helpers (Blackwell FFMA2, identical per-lane fp32 rounding) ----
__device__ __forceinline__ ull pack2(float lo, float hi) {
    ull r;
    asm("mov.b64 %0, {%1, %2};" : "=l"(r)
        : "r"(__float_as_uint(lo)), "r"(__float_as_uint(hi)));
    return r;
}
__device__ __forceinline__ void unpack2(ull v, float& lo, float& hi) {
    unsigned a, b;
    asm("mov.b64 {%0, %1}, %2;" : "=r"(a), "=r"(b) : "l"(v));
    lo = __uint_as_float(a); hi = __uint_as_float(b);
}
__device__ __forceinline__ ull fma2(ull a, ull b, ull c) {
    ull d;
    asm("fma.rn.f32x2 %0, %1, %2, %3;" : "=l"(d) : "l"(a), "l"(b), "l"(c));
    return d;
}

// ============================================================================
// GEMM1 (R4-verified structure; ONLY change: B pairs loaded as ulonglong2
// straight from smem instead of float4+pack2 -> 8 fewer MOVs per kk).
// g_h1[m,n] = sum_k x[m,k]*w1[n,k] + b1[n], ascending-k (bitwise-exact).
// ============================================================================
__global__ __launch_bounds__(256) void gemm1_kernel(const float* __restrict__ A,
                                                    const float* __restrict__ W,
                                                    const float* __restrict__ bias) {
    __shared__ __align__(16) float As[16][132];
    __shared__ __align__(16) float Bs[16][132];
    const int tid  = threadIdx.x;
    const int row0 = blockIdx.y * 128;
    const int col0 = blockIdx.x * 128;
    const int tx = tid & 15;
    const int ty = tid >> 4;
    const int lm = tid >> 2;
    const int lk = (tid & 3) * 4;

    const float* Ap = A + (size_t)(row0 + lm) * ND + lk;
    const float* Bp = W + (size_t)(col0 + lm) * ND + lk;

    ull acc[8][4];
#pragma unroll
    for (int i = 0; i < 8; i++)
#pragma unroll
        for (int j = 0; j < 4; j++) acc[i][j] = 0ull;

    float4 pa0 = *(const float4*)(Ap);
    float4 pa1 = *(const float4*)(Ap + (size_t)64 * ND);
    float4 pb0 = *(const float4*)(Bp);
    float4 pb1 = *(const float4*)(Bp + (size_t)64 * ND);

#pragma unroll 1
    for (int kt = 0; kt < 32; kt++) {
        As[lk + 0][lm] = pa0.x; As[lk + 1][lm] = pa0.y; As[lk + 2][lm] = pa0.z; As[lk + 3][lm] = pa0.w;
        As[lk + 0][lm + 64] = pa1.x; As[lk + 1][lm + 64] = pa1.y; As[lk + 2][lm + 64] = pa1.z; As[lk + 3][lm + 64] = pa1.w;
        Bs[lk + 0][lm] = pb0.x; Bs[lk + 1][lm] = pb0.y; Bs[lk + 2][lm] = pb0.z; Bs[lk + 3][lm] = pb0.w;
        Bs[lk + 0][lm + 64] = pb1.x; Bs[lk + 1][lm + 64] = pb1.y; Bs[lk + 2][lm + 64] = pb1.z; Bs[lk + 3][lm + 64] = pb1.w;
        __syncthreads();

        if (kt < 31) {
            const float* Ap2 = Ap + (kt + 1) * 16;
            const float* Bp2 = Bp + (kt + 1) * 16;
            pa0 = *(const float4*)(Ap2);
            pa1 = *(const float4*)(Ap2 + (size_t)64 * ND);
            pb0 = *(const float4*)(Bp2);
            pb1 = *(const float4*)(Bp2 + (size_t)64 * ND);
        }

#pragma unroll
        for (int kk = 0; kk < 16; kk++) {
            float4 a0 = *(const float4*)&As[kk][ty * 8];
            float4 a1 = *(const float4*)&As[kk][ty * 8 + 4];
            ulonglong2 bl0 = *(const ulonglong2*)&Bs[kk][tx * 8];
            ulonglong2 bl1 = *(const ulonglong2*)&Bs[kk][tx * 8 + 4];
            float av[8] = {a0.x, a0.y, a0.z, a0.w, a1.x, a1.y, a1.z, a1.w};
#pragma unroll
            for (int i = 0; i < 8; i++) {
                ull aa = pack2(av[i], av[i]);
                acc[i][0] = fma2(aa, bl0.x, acc[i][0]);
                acc[i][1] = fma2(aa, bl0.y, acc[i][1]);
                acc[i][2] = fma2(aa, bl1.x, acc[i][2]);
                acc[i][3] = fma2(aa, bl1.y, acc[i][3]);
            }
        }
        __syncthreads();
    }

    float bv[8];
#pragma unroll
    for (int j = 0; j < 8; j++) bv[j] = bias[col0 + tx * 8 + j];
#pragma unroll
    for (int i = 0; i < 8; i++) {
        float o[8];
        unpack2(acc[i][0], o[0], o[1]);
        unpack2(acc[i][1], o[2], o[3]);
        unpack2(acc[i][2], o[4], o[5]);
        unpack2(acc[i][3], o[6], o[7]);
#pragma unroll
        for (int j = 0; j < 8; j++) o[j] += bv[j];
        float* cp = g_h1 + (size_t)(row0 + ty * 8 + i) * NH + col0 + tx * 8;
        ((float4*)cp)[0] = make_float4(o[0], o[1], o[2], o[3]);
        ((float4*)cp)[1] = make_float4(o[4], o[5], o[6], o[7]);
    }
}

// ============================================================================
// block-wide reduction (blockDim multiple of 32, <= 256)
// ============================================================================
__device__ __forceinline__ float block_reduce_sum(float val) {
    __shared__ float sm[32];
    const int tid = threadIdx.x;
#pragma unroll
    for (int o = 16; o; o >>= 1) val += __shfl_down_sync(0xffffffffu, val, o);
    if ((tid & 31) == 0) sm[tid >> 5] = val;
    __syncthreads();
    if (tid < 32) {
        const int nw = (blockDim.x + 31) >> 5;
        float v = (tid < nw) ? sm[tid] : 0.f;
#pragma unroll
        for (int o = 4; o; o >>= 1) v += __shfl_down_sync(0xffffffffu, v, o);
        if (tid == 0) sm[0] = v;
    }
    __syncthreads();
    float r = sm[0];
    __syncthreads();
    return r;
}

// ============================================================================
// LN1 stats only: mean & inv-std per row of g_h1.
// ============================================================================
__global__ __launch_bounds__(256) void ln1_stats_kernel() {
    const float* p = g_h1 + (size_t)blockIdx.x * NH;
    const int tid = threadIdx.x;
    float4 v = ((const float4*)p)[tid];
    float s = (v.x + v.y) + (v.z + v.w);
    float total = block_reduce_sum(s);
    float mean = total * (1.0f / NH);
    float d0 = v.x - mean, d1 = v.y - mean, d2 = v.z - mean, d3 = v.w - mean;
    float sq = (d0 * d0 + d1 * d1) + (d2 * d2 + d3 * d3);
    float tot2 = block_reduce_sum(sq);
    float inv = 1.0f / sqrtf(tot2 * (1.0f / NH) + 1e-5f);
    if (tid == 0) { g_mean[blockIdx.x] = mean; g_inv[blockIdx.x] = inv; }
}

// ============================================================================
// LIF layer 1 with inline LayerNorm (R4-verified byte-spike version).
// ============================================================================
__global__ __launch_bounds__(128) void lif1_kernel(const float* __restrict__ g1,
                                                   const float* __restrict__ be1) {
    const int idx = blockIdx.x * 128 + threadIdx.x;   // NB*NH = 32768
    const int b = idx >> 10;
    const int h = idx & (NH - 1);
    const int tid = threadIdx.x;

    __shared__ float s_mean[NT];
    __shared__ float s_inv[NT];
#pragma unroll
    for (int t = tid; t < NT; t += 128) {
        s_mean[t] = g_mean[b * NT + t];
        s_inv[t]  = g_inv [b * NT + t];
    }
    __syncthreads();

    const float gh  = g1[h];
    const float beh = be1[h];
    const float* p = g_h1 + (size_t)b * NT * NH + h;
    unsigned char* q = g_s1 + (size_t)b * NT * NH + h;
    float v = 0.f;
#pragma unroll 1
    for (int t0 = 0; t0 < NT; t0 += 16) {
        float xb[16];
#pragma unroll
        for (int i = 0; i < 16; i++) xb[i] = p[(size_t)(t0 + i) * NH];
        unsigned char sb[16];
#pragma unroll
        for (int i = 0; i < 16; i++) {
            float d = xb[i] - s_mean[t0 + i];
            float val = d * s_inv[t0 + i] * gh + beh;
            v = v + (val - v) * 0.5f;       // TAU = 2
            bool sp = (v >= 1.0f);          // V_TH = 1
            sb[i] = sp ? (unsigned char)1 : (unsigned char)0;
            v = sp ? 0.f : v;               // hard reset
        }
#pragma unroll
        for (int i = 0; i < 16; i++) q[(size_t)(t0 + i) * NH] = sb[i];
    }
}

// ============================================================================
// fc2 (sparse gmem gather, L1-resident w2t) + fused LayerNorm2 (R4-verified).
// ============================================================================
__global__ __launch_bounds__(128) void fc2ln2_kernel(const float* __restrict__ b2,
                                                     const float* __restrict__ g2,
                                                     const float* __restrict__ be2) {
    const int row = blockIdx.x;
    const int tid = threadIdx.x;
    const unsigned char* srow = g_s1 + (size_t)row * NH;

    ull m8 = ((const ull*)srow)[tid];           // 8 spike bytes
    int c = __popcll(m8);
    int pre = c;
#pragma unroll
    for (int o = 1; o < 32; o <<= 1) {
        int n = __shfl_up_sync(0xffffffffu, pre, o);
        if ((tid & 31) >= o) pre += n;
    }
    __shared__ int wsum[4];
    __shared__ unsigned short list[NH];
    __shared__ int s_total;
    if ((tid & 31) == 31) wsum[tid >> 5] = pre;
    __syncthreads();
    int base = 0;
#pragma unroll
    for (int w = 0; w < 4; w++)
        if (w < (tid >> 5)) base += wsum[w];
    int off = base + pre - c;
#pragma unroll
    for (int k = 0; k < 8; k++)
        if ((m8 >> (8 * k)) & 1ull) list[off++] = (unsigned short)(tid * 8 + k);
    if (tid == 127) s_total = base + pre;
    __syncthreads();

    const int cnt = s_total;
    const float* wbase = g_w2t + tid * 4;
    float4 acc = make_float4(0.f, 0.f, 0.f, 0.f);
    int i = 0;
    for (; i + 4 <= cnt; i += 4) {
        int h0 = list[i], h1 = list[i + 1], h2 = list[i + 2], h3 = list[i + 3];
        float4 w0 = *(const float4*)(wbase + (size_t)h0 * ND);
        float4 w1 = *(const float4*)(wbase + (size_t)h1 * ND);
        float4 w2v = *(const float4*)(wbase + (size_t)h2 * ND);
        float4 w3 = *(const float4*)(wbase + (size_t)h3 * ND);
        acc.x += w0.x; acc.y += w0.y; acc.z += w0.z; acc.w += w0.w;
        acc.x += w1.x; acc.y += w1.y; acc.z += w1.z; acc.w += w1.w;
        acc.x += w2v.x; acc.y += w2v.y; acc.z += w2v.z; acc.w += w2v.w;
        acc.x += w3.x; acc.y += w3.y; acc.z += w3.z; acc.w += w3.w;
    }
    for (; i < cnt; i++) {
        float4 w0 = *(const float4*)(wbase + (size_t)list[i] * ND);
        acc.x += w0.x; acc.y += w0.y; acc.z += w0.z; acc.w += w0.w;
    }
    float4 bb = ((const float4*)b2)[tid];
    acc.x += bb.x; acc.y += bb.y; acc.z += bb.z; acc.w += bb.w;

    // ---- fused LayerNorm2 ----
    float s = (acc.x + acc.y) + (acc.z + acc.w);
    float total = block_reduce_sum(s);
    float mean = total * (1.0f / ND);
    float d0 = acc.x - mean, d1 = acc.y - mean, d2 = acc.z - mean, d3 = acc.w - mean;
    float sq = (d0 * d0 + d1 * d1) + (d2 * d2 + d3 * d3);
    float tot2 = block_reduce_sum(sq);
    float inv = 1.0f / sqrtf(tot2 * (1.0f / ND) + 1e-5f);
    float4 gg = ((const float4*)g2)[tid];
    float4 bv = ((const float4*)be2)[tid];
    float4 o;
    o.x = d0 * inv * gg.x + bv.x;
    o.y = d1 * inv * gg.y + bv.y;
    o.z = d2 * inv * gg.z + bv.z;
    o.w = d3 * inv * gg.w + bv.w;
    ((float4*)(g_y + (size_t)row * ND))[tid] = o;
}

// ============================================================================
// LIF layer 2 + residual (R4-verified 16-deep config): out = x + spike2.
// ============================================================================
__global__ __launch_bounds__(64) void lif2_kernel(const float* __restrict__ x,
                                                  float* __restrict__ out) {
    const int idx = blockIdx.x * 64 + threadIdx.x;    // NB*ND = 16384
    const int b = idx >> 9;
    const int d = idx & (ND - 1);
    const float* py = g_y + (size_t)b * NT * ND + d;
    const float* px = x + (size_t)b * NT * ND + d;
    float* po = out + (size_t)b * NT * ND + d;
    float v = 0.f;
#pragma unroll 1
    for (int t0 = 0; t0 < NT; t0 += 16) {
        float yb[16], xb[16];
#pragma unroll
        for (int i = 0; i < 16; i++) yb[i] = py[(size_t)(t0 + i) * ND];
#pragma unroll
        for (int i = 0; i < 16; i++) xb[i] = px[(size_t)(t0 + i) * ND];
        float ob[16];
#pragma unroll
        for (int i = 0; i < 16; i++) {
            v = v + (yb[i] - v) * 0.5f;
            bool sp = (v >= 1.0f);
            ob[i] = xb[i] + (sp ? 1.0f : 0.0f);
            v = sp ? 0.f : v;
        }
#pragma unroll
        for (int i = 0; i < 16; i++) po[(size_t)(t0 + i) * ND] = ob[i];
    }
}

// ============================================================================
// w2 [D, H] -> g_w2t [H, D]
// ============================================================================
__global__ void transpose_kernel(const float* __restrict__ w2) {
    __shared__ float tile[32][33];
    const int h0 = blockIdx.x * 32;
    const int d0 = blockIdx.y * 32;
    tile[threadIdx.y][threadIdx.x] = w2[(size_t)(d0 + threadIdx.y) * NH + h0 + threadIdx.x];
    __syncthreads();
    g_w2t[(size_t)(h0 + threadIdx.y) * ND + d0 + threadIdx.x] = tile[threadIdx.x][threadIdx.y];
}

// ============================================================================
extern "C" void kernel_launch(void* const* d_in, const int* in_sizes, int n_in,
                              void* d_out, int out_size) {
    const float* x   = (const float*)d_in[0];
    const float* w1  = (const float*)d_in[1];
    const float* b1  = (const float*)d_in[2];
    const float* g1  = (const float*)d_in[3];
    const float* be1 = (const float*)d_in[4];
    const float* w2  = (const float*)d_in[5];
    const float* b2  = (const float*)d_in[6];
    const float* g2  = (const float*)d_in[7];
    const float* be2 = (const float*)d_in[8];
    float* out = (float*)d_out;

    transpose_kernel<<<dim3(NH / 32, ND / 32), dim3(32, 32)>>>(w2);
    gemm1_kernel<<<dim3(NH / 128, NM / 128), 256>>>(x, w1, b1);
    ln1_stats_kernel<<<NM, 256>>>();
    lif1_kernel<<<(NB * NH) / 128, 128>>>(g1, be1);
    fc2ln2_kernel<<<NM, 128>>>(b2, g2, be2);
    lif2_kernel<<<(NB * ND) / 64, 64>>>(x, out);
}